// round 1
// baseline (speedup 1.0000x reference)
#include <cuda_runtime.h>
#include <math.h>

// ---------------- problem constants ----------------
#define Bx 16
#define Sx 384
#define Hx 768
#define DKx 64
#define ESSx 6
#define WHOLEx 8
#define HEADERx 9
#define IGx 672
#define IPx 960
#define H2x 1536
#define Px 73920              // S*(S+1)/2
#define Mx (Bx*Sx)            // 6144

// ---------------- scratch (device globals; no allocations) ----------------
__device__ float g_cos[Sx*32];
__device__ float g_sin[Sx*32];
__device__ float g_lin[Mx*576];                    // linear outputs pre-rope (max 576 ch)
__device__ float g_hid[Mx*IPx];                    // MLP hidden (max 960)
__device__ float g_tsq[Bx*Sx*DKx];
__device__ float g_tsk[Bx*Sx*DKx];
__device__ float g_qg [Bx*HEADERx*Sx*DKx];
__device__ float g_kg [Bx*HEADERx*Sx*DKx];
__device__ float g_scg[(size_t)Bx*HEADERx*Sx*Sx];  // graph scores (9 heads)  85MB
__device__ float g_adj[(size_t)Bx*HEADERx*Sx*Sx];  // adjacency               85MB
__device__ float g_hr [(size_t)HEADERx*Bx*Sx*Hx];  // per-relation features  170MB
__device__ float g_feat[Mx*Hx];
__device__ float g_agg [Mx*Hx];
__device__ float g_inp [Mx*H2x];
__device__ float g_tq[Bx*Sx*DKx];
__device__ float g_tk[Bx*Sx*DKx];
__device__ float g_qp[Bx*ESSx*Sx*DKx];
__device__ float g_kp[Bx*ESSx*Sx*DKx];
__device__ float g_stg[(size_t)Bx*Sx*Sx];
__device__ float g_stp[(size_t)Bx*Sx*Sx];
__device__ float g_sp [(size_t)Bx*ESSx*Sx*Sx];

// ---------------- rope tables (double precision, matches numpy f64 sin/cos) ----------------
__global__ void k_init_rope() {
    int idx = blockIdx.x * blockDim.x + threadIdx.x;
    if (idx >= Sx * 32) return;
    int p = idx / 32, i = idx & 31;
    double theta = (double)p * pow(10000.0, -(double)i / 32.0);
    g_cos[idx] = (float)cos(theta);
    g_sin[idx] = (float)sin(theta);
}

// ---------------- generic batched GEMM:  C[z] = act( A[z][M,K] @ W[z][N,K]^T * scale + bias ) ----------------
// BM=BN=128, BK=16, 256 threads, 8x8 per thread. M must be a multiple of 128; K a multiple of 16.
__global__ void __launch_bounds__(256) k_gemm_wt(
    const float* __restrict__ A, long astr,
    const float* __restrict__ W, long wstr,
    const float* __restrict__ bias,
    float* __restrict__ C, long cstr,
    int M, int N, int K, int relu, float scale)
{
    const float* Az = A + (long)blockIdx.z * astr;
    const float* Wz = W + (long)blockIdx.z * wstr;
    float* Cz = C + (long)blockIdx.z * cstr;

    __shared__ float As[16][128];
    __shared__ float Bs[16][128];

    int tid  = threadIdx.x;
    int row0 = blockIdx.y * 128;
    int col0 = blockIdx.x * 128;

    int lr = tid >> 1;            // 0..127
    int lk = (tid & 1) * 8;       // 0 or 8
    int tr = (tid >> 4) * 4;      // 0..60
    int tc = (tid & 15) * 4;      // 0..60

    float acc[8][8];
#pragma unroll
    for (int i = 0; i < 8; ++i)
#pragma unroll
        for (int j = 0; j < 8; ++j) acc[i][j] = 0.f;

    for (int k0 = 0; k0 < K; k0 += 16) {
        // A tile
        const float* ap = Az + (long)(row0 + lr) * K + k0 + lk;
        float4 a0 = *(const float4*)ap;
        float4 a1 = *(const float4*)(ap + 4);
        As[lk+0][lr] = a0.x; As[lk+1][lr] = a0.y; As[lk+2][lr] = a0.z; As[lk+3][lr] = a0.w;
        As[lk+4][lr] = a1.x; As[lk+5][lr] = a1.y; As[lk+6][lr] = a1.z; As[lk+7][lr] = a1.w;
        // W tile (row n, guarded)
        int n = col0 + lr;
        float4 b0 = make_float4(0.f,0.f,0.f,0.f), b1 = b0;
        if (n < N) {
            const float* wp = Wz + (long)n * K + k0 + lk;
            b0 = *(const float4*)wp;
            b1 = *(const float4*)(wp + 4);
        }
        Bs[lk+0][lr] = b0.x; Bs[lk+1][lr] = b0.y; Bs[lk+2][lr] = b0.z; Bs[lk+3][lr] = b0.w;
        Bs[lk+4][lr] = b1.x; Bs[lk+5][lr] = b1.y; Bs[lk+6][lr] = b1.z; Bs[lk+7][lr] = b1.w;
        __syncthreads();

#pragma unroll
        for (int kk = 0; kk < 16; ++kk) {
            float4 t0 = *(const float4*)&As[kk][tr];
            float4 t1 = *(const float4*)&As[kk][tr + 64];
            float4 u0 = *(const float4*)&Bs[kk][tc];
            float4 u1 = *(const float4*)&Bs[kk][tc + 64];
            float a[8] = {t0.x,t0.y,t0.z,t0.w,t1.x,t1.y,t1.z,t1.w};
            float b[8] = {u0.x,u0.y,u0.z,u0.w,u1.x,u1.y,u1.z,u1.w};
#pragma unroll
            for (int i = 0; i < 8; ++i)
#pragma unroll
                for (int j = 0; j < 8; ++j)
                    acc[i][j] = fmaf(a[i], b[j], acc[i][j]);
        }
        __syncthreads();
    }

#pragma unroll
    for (int i = 0; i < 8; ++i) {
        int r = row0 + tr + (i < 4 ? i : 60 + i);
#pragma unroll
        for (int j = 0; j < 8; ++j) {
            int c = col0 + tc + (j < 4 ? j : 60 + j);
            if (c < N) {
                float v = acc[i][j] * scale + (bias ? bias[c] : 0.f);
                if (relu) v = fmaxf(v, 0.f);
                Cz[(long)r * N + c] = v;
            }
        }
    }
}

// ---------------- mask + RoPE + head split:  lin[B,S,nH*64] -> out[B,nH,S,64] ----------------
__global__ void k_rope(const float* __restrict__ lin, const float* __restrict__ mask,
                       float* __restrict__ out, int nH)
{
    int bs = blockIdx.x;
    int b = bs / Sx, s = bs % Sx;
    float m = mask[bs];
    int t = threadIdx.x;            // nH*32 threads
    int h = t >> 5, i = t & 31;
    float c  = g_cos[s*32 + i];
    float sn = g_sin[s*32 + i];
    const float* lp = lin + (long)bs * nH * 64 + h * 64 + 2*i;
    float x0 = lp[0] * m, x1 = lp[1] * m;
    float* op = out + (((long)(b*nH + h)) * Sx + s) * 64 + 2*i;
    op[0] = x0 * c - x1 * sn;
    op[1] = x1 * c + x0 * sn;
}

// ---------------- symmetric softmax -> adj ----------------
__global__ void k_adj(const float* __restrict__ score, float* __restrict__ adj)
{
    int blk = blockIdx.x;
    int i = blk % Sx;
    long bh = blk / Sx;
    const float* sc = score + bh * (long)(Sx*Sx);
    float* out = adj + bh * (long)(Sx*Sx) + (long)i * Sx;
    int t = threadIdx.x; // 128
    float v[3];
#pragma unroll
    for (int u = 0; u < 3; ++u) {
        int j = t + u * 128;
        v[u] = (j >= i) ? sc[(long)i*Sx + j] : sc[(long)j*Sx + i];
    }
    __shared__ float red[128];
    float m = fmaxf(v[0], fmaxf(v[1], v[2]));
    red[t] = m; __syncthreads();
#pragma unroll
    for (int st = 64; st > 0; st >>= 1) {
        if (t < st) red[t] = fmaxf(red[t], red[t + st]);
        __syncthreads();
    }
    m = red[0]; __syncthreads();
    float e0 = expf(v[0]-m), e1 = expf(v[1]-m), e2 = expf(v[2]-m);
    red[t] = e0 + e1 + e2; __syncthreads();
#pragma unroll
    for (int st = 64; st > 0; st >>= 1) {
        if (t < st) red[t] += red[t + st];
        __syncthreads();
    }
    float is = 1.f / red[0];
    out[t      ] = (v[0] != 0.f) ? e0 * is : 0.f;
    out[t + 128] = (v[1] != 0.f) ? e1 * is : 0.f;
    out[t + 256] = (v[2] != 0.f) ? e2 * is : 0.f;
}

// ---------------- fused aggsum[b,s,o] = sum_r relu( adj[b,r] @ hr[r,b] )[s,o] ----------------
// BM=128 (s), BN=64 (o), BK=16, 256 threads, 8x4 per thread.
__global__ void __launch_bounds__(256) k_agg(const float* __restrict__ adj,
                                             const float* __restrict__ hr,
                                             float* __restrict__ out)
{
    int b    = blockIdx.z;
    int row0 = blockIdx.y * 128;
    int col0 = blockIdx.x * 64;

    __shared__ float As[16][128];
    __shared__ float Bs[16][64];

    int tid = threadIdx.x;
    int lr  = tid >> 1;
    int lk  = (tid & 1) * 8;
    int lkb = tid >> 4;            // 0..15
    int lnb = (tid & 15) * 4;      // 0..60
    int tr  = (tid >> 4) * 4;
    int tc  = (tid & 15) * 4;

    float sum[8][4];
#pragma unroll
    for (int i = 0; i < 8; ++i)
#pragma unroll
        for (int j = 0; j < 4; ++j) sum[i][j] = 0.f;

    for (int r = 0; r < HEADERx; ++r) {
        const float* adjbr = adj + ((long)(b*HEADERx + r)) * Sx * Sx;
        const float* hrrb  = hr  + ((long)(r*Bx + b)) * Sx * Hx;
        float acc[8][4];
#pragma unroll
        for (int i = 0; i < 8; ++i)
#pragma unroll
            for (int j = 0; j < 4; ++j) acc[i][j] = 0.f;

        for (int k0 = 0; k0 < Sx; k0 += 16) {
            const float* ap = adjbr + (long)(row0 + lr) * Sx + k0 + lk;
            float4 a0 = *(const float4*)ap;
            float4 a1 = *(const float4*)(ap + 4);
            As[lk+0][lr] = a0.x; As[lk+1][lr] = a0.y; As[lk+2][lr] = a0.z; As[lk+3][lr] = a0.w;
            As[lk+4][lr] = a1.x; As[lk+5][lr] = a1.y; As[lk+6][lr] = a1.z; As[lk+7][lr] = a1.w;
            const float* bp = hrrb + (long)(k0 + lkb) * Hx + col0 + lnb;
            *(float4*)&Bs[lkb][lnb] = *(const float4*)bp;
            __syncthreads();
#pragma unroll
            for (int kk = 0; kk < 16; ++kk) {
                float4 t0 = *(const float4*)&As[kk][tr];
                float4 t1 = *(const float4*)&As[kk][tr + 64];
                float4 u0 = *(const float4*)&Bs[kk][tc];
                float a[8] = {t0.x,t0.y,t0.z,t0.w,t1.x,t1.y,t1.z,t1.w};
                float bb[4] = {u0.x,u0.y,u0.z,u0.w};
#pragma unroll
                for (int i = 0; i < 8; ++i)
#pragma unroll
                    for (int j = 0; j < 4; ++j)
                        acc[i][j] = fmaf(a[i], bb[j], acc[i][j]);
            }
            __syncthreads();
        }
#pragma unroll
        for (int i = 0; i < 8; ++i)
#pragma unroll
            for (int j = 0; j < 4; ++j)
                sum[i][j] += fmaxf(acc[i][j], 0.f);
    }

#pragma unroll
    for (int i = 0; i < 8; ++i) {
        int s = row0 + tr + (i < 4 ? i : 60 + i);
#pragma unroll
        for (int j = 0; j < 4; ++j) {
            int o = col0 + tc + j;
            out[((long)b * Sx + s) * Hx + o] = sum[i][j];
        }
    }
}

// ---------------- feat = layernorm( relu(agg)/9 ) ----------------
__global__ void k_ln(const float* __restrict__ a, float* __restrict__ o)
{
    long bs = blockIdx.x;
    const float* x = a + bs * Hx;
    float* y = o + bs * Hx;
    int t = threadIdx.x; // 256
    float v[3];
    float s = 0.f;
#pragma unroll
    for (int u = 0; u < 3; ++u) {
        v[u] = fmaxf(x[t + u*256], 0.f) * (1.f/9.f);
        s += v[u];
    }
    __shared__ float red[256];
    red[t] = s; __syncthreads();
#pragma unroll
    for (int st = 128; st > 0; st >>= 1) {
        if (t < st) red[t] += red[t + st];
        __syncthreads();
    }
    float mean = red[0] * (1.f/768.f); __syncthreads();
    float s2 = 0.f;
#pragma unroll
    for (int u = 0; u < 3; ++u) { float d = v[u] - mean; s2 += d*d; }
    red[t] = s2; __syncthreads();
#pragma unroll
    for (int st = 128; st > 0; st >>= 1) {
        if (t < st) red[t] += red[t + st];
        __syncthreads();
    }
    float var = red[0] * (1.f/768.f);
    float rr = rsqrtf(var + 1e-5f);
#pragma unroll
    for (int u = 0; u < 3; ++u) y[t + u*256] = (v[u] - mean) * rr;
}

// ---------------- inp = concat(x, feat) ----------------
__global__ void k_concat(const float* __restrict__ x, const float* __restrict__ feat,
                         float* __restrict__ inp)
{
    long idx = (long)blockIdx.x * blockDim.x + threadIdx.x;
    if (idx >= (long)Mx * H2x) return;
    long row = idx / H2x;
    int c = (int)(idx % H2x);
    inp[idx] = (c < Hx) ? x[row * Hx + c] : feat[row * Hx + (c - Hx)];
}

// ---------------- gather upper-triangle pairs -> out[B,P,16] ----------------
__global__ void k_pairs(const float* __restrict__ sp, const float* __restrict__ stp,
                        const float* __restrict__ sg, const float* __restrict__ stg,
                        float* __restrict__ out)
{
    int i = blockIdx.x, b = blockIdx.y, j = threadIdx.x;
    if (j < i) return;
    long p  = (long)i * (2*Sx - i + 1) / 2 + (j - i);
    long ss = (long)Sx * Sx;
    long ij = (long)i * Sx + j;
    const float* spb = sp + (long)b * ESSx * ss + ij;
    const float* sgb = sg + (long)b * HEADERx * ss + ij;
    float4 o0, o1, o2, o3;
    o0.x = spb[0];     o0.y = spb[ss];   o0.z = spb[2*ss]; o0.w = spb[3*ss];
    o1.x = spb[4*ss];  o1.y = spb[5*ss];
    o1.z = fmaxf(stp[(long)b*ss + ij], 0.f);
    o1.w = sgb[0];
    o2.x = sgb[ss];    o2.y = sgb[2*ss]; o2.z = sgb[3*ss]; o2.w = sgb[4*ss];
    o3.x = sgb[5*ss];  o3.y = sgb[6*ss]; o3.z = sgb[7*ss];
    o3.w = fmaxf(stg[(long)b*ss + ij], 0.f);
    float4* op = (float4*)(out + ((long)b * Px + p) * 16);
    op[0] = o0; op[1] = o1; op[2] = o2; op[3] = o3;
}

// ---------------- host ----------------
static void launch_gemm(const float* A, long astr, const float* W, long wstr,
                        const float* bias, float* C, long cstr,
                        int M, int N, int K, int relu, float scale, int Z)
{
    dim3 grid((N + 127) / 128, M / 128, Z);
    k_gemm_wt<<<grid, 256>>>(A, astr, W, wstr, bias, C, cstr, M, N, K, relu, scale);
}

extern "C" void kernel_launch(void* const* d_in, const int* in_sizes, int n_in,
                              void* d_out, int out_size)
{
    const float* x          = (const float*)d_in[0];
    const float* amask      = (const float*)d_in[1];
    const float* wq4gt_w    = (const float*)d_in[2];
    const float* wq4gt_b    = (const float*)d_in[3];
    const float* wk4gt_w    = (const float*)d_in[4];
    const float* wk4gt_b    = (const float*)d_in[5];
    const float* wq4g_rep_w = (const float*)d_in[6];
    const float* wq4g_rep_b = (const float*)d_in[7];
    const float* wq4g_sc_w  = (const float*)d_in[8];
    const float* wq4g_sc_b  = (const float*)d_in[9];
    const float* wk4g_rep_w = (const float*)d_in[10];
    const float* wk4g_rep_b = (const float*)d_in[11];
    const float* wk4g_sc_w  = (const float*)d_in[12];
    const float* wk4g_sc_b  = (const float*)d_in[13];
    const float* rgat_w     = (const float*)d_in[14];
    const float* wq4t_w     = (const float*)d_in[15];
    const float* wq4t_b     = (const float*)d_in[16];
    const float* wk4t_w     = (const float*)d_in[17];
    const float* wk4t_b     = (const float*)d_in[18];
    const float* wq_rep_w   = (const float*)d_in[19];
    const float* wq_rep_b   = (const float*)d_in[20];
    const float* wq_sc_w    = (const float*)d_in[21];
    const float* wq_sc_b    = (const float*)d_in[22];
    const float* wk_rep_w   = (const float*)d_in[23];
    const float* wk_rep_b   = (const float*)d_in[24];
    const float* wk_sc_w    = (const float*)d_in[25];
    const float* wk_sc_b    = (const float*)d_in[26];
    float* out = (float*)d_out;

    float *lin,*hid,*tsq,*tsk,*qg,*kg,*scg,*adj,*hr,*feat,*agg,*inp,*tq,*tk,*qp,*kp,*stg,*stp,*sp;
    cudaGetSymbolAddress((void**)&lin,  g_lin);
    cudaGetSymbolAddress((void**)&hid,  g_hid);
    cudaGetSymbolAddress((void**)&tsq,  g_tsq);
    cudaGetSymbolAddress((void**)&tsk,  g_tsk);
    cudaGetSymbolAddress((void**)&qg,   g_qg);
    cudaGetSymbolAddress((void**)&kg,   g_kg);
    cudaGetSymbolAddress((void**)&scg,  g_scg);
    cudaGetSymbolAddress((void**)&adj,  g_adj);
    cudaGetSymbolAddress((void**)&hr,   g_hr);
    cudaGetSymbolAddress((void**)&feat, g_feat);
    cudaGetSymbolAddress((void**)&agg,  g_agg);
    cudaGetSymbolAddress((void**)&inp,  g_inp);
    cudaGetSymbolAddress((void**)&tq,   g_tq);
    cudaGetSymbolAddress((void**)&tk,   g_tk);
    cudaGetSymbolAddress((void**)&qp,   g_qp);
    cudaGetSymbolAddress((void**)&kp,   g_kp);
    cudaGetSymbolAddress((void**)&stg,  g_stg);
    cudaGetSymbolAddress((void**)&stp,  g_stp);
    cudaGetSymbolAddress((void**)&sp,   g_sp);

    const float inv = 0.125f;            // 1/sqrt(64)
    const long sd  = (long)Sx * DKx;
    const long ss  = (long)Sx * Sx;

    k_init_rope<<<48, 256>>>();

    // ---- graph threshold heads ----
    launch_gemm(x, 0, wq4gt_w, 0, wq4gt_b, lin, 0, Mx, 64, Hx, 0, 1.f, 1);
    k_rope<<<Mx, 32>>>(lin, amask, tsq, 1);
    launch_gemm(x, 0, wk4gt_w, 0, wk4gt_b, lin, 0, Mx, 64, Hx, 0, 1.f, 1);
    k_rope<<<Mx, 32>>>(lin, amask, tsk, 1);
    launch_gemm(tsq, sd, tsk, sd, nullptr, stg, ss, Sx, Sx, DKx, 0, inv, Bx);

    // ---- graph q/k (9 heads) ----
    launch_gemm(x, 0, wq4g_rep_w, 0, wq4g_rep_b, hid, 0, Mx, IGx, Hx, 1, 1.f, 1);
    launch_gemm(hid, 0, wq4g_sc_w, 0, wq4g_sc_b, lin, 0, Mx, 576, IGx, 0, 1.f, 1);
    k_rope<<<Mx, 288>>>(lin, amask, qg, 9);
    launch_gemm(x, 0, wk4g_rep_w, 0, wk4g_rep_b, hid, 0, Mx, IGx, Hx, 1, 1.f, 1);
    launch_gemm(hid, 0, wk4g_sc_w, 0, wk4g_sc_b, lin, 0, Mx, 576, IGx, 0, 1.f, 1);
    k_rope<<<Mx, 288>>>(lin, amask, kg, 9);
    launch_gemm(qg, sd, kg, sd, nullptr, scg, ss, Sx, Sx, DKx, 0, inv, Bx*HEADERx);
    k_adj<<<Bx*HEADERx*Sx, 128>>>(scg, adj);

    // ---- RGAT (2 layers) ----
    const float* f = x;
    for (int l = 0; l < 2; ++l) {
        launch_gemm(f, 0, rgat_w + (long)l*HEADERx*Hx*Hx, (long)Hx*Hx, nullptr,
                    hr, (long)Bx*Sx*Hx, Mx, Hx, Hx, 0, 1.f, HEADERx);
        k_agg<<<dim3(Hx/64, Sx/128, Bx), 256>>>(adj, hr, agg);
        k_ln<<<Mx, 256>>>(agg, feat);
        f = feat;
    }

    // ---- concat ----
    k_concat<<<((long)Mx*H2x + 255)/256, 256>>>(x, feat, inp);

    // ---- prediction threshold heads ----
    launch_gemm(inp, 0, wq4t_w, 0, wq4t_b, lin, 0, Mx, 64, H2x, 0, 1.f, 1);
    k_rope<<<Mx, 32>>>(lin, amask, tq, 1);
    launch_gemm(inp, 0, wk4t_w, 0, wk4t_b, lin, 0, Mx, 64, H2x, 0, 1.f, 1);
    k_rope<<<Mx, 32>>>(lin, amask, tk, 1);
    launch_gemm(tq, sd, tk, sd, nullptr, stp, ss, Sx, Sx, DKx, 0, inv, Bx);

    // ---- prediction q/k (6 heads) ----
    launch_gemm(inp, 0, wq_rep_w, 0, wq_rep_b, hid, 0, Mx, IPx, H2x, 1, 1.f, 1);
    launch_gemm(hid, 0, wq_sc_w, 0, wq_sc_b, lin, 0, Mx, 384, IPx, 0, 1.f, 1);
    k_rope<<<Mx, 192>>>(lin, amask, qp, 6);
    launch_gemm(inp, 0, wk_rep_w, 0, wk_rep_b, hid, 0, Mx, IPx, H2x, 1, 1.f, 1);
    launch_gemm(hid, 0, wk_sc_w, 0, wk_sc_b, lin, 0, Mx, 384, IPx, 0, 1.f, 1);
    k_rope<<<Mx, 192>>>(lin, amask, kp, 6);
    launch_gemm(qp, sd, kp, sd, nullptr, sp, ss, Sx, Sx, DKx, 0, inv, Bx*ESSx);

    // ---- final gather ----
    k_pairs<<<dim3(Sx, Bx), Sx>>>(sp, stp, scg, stg, out);
}

// round 2
// speedup vs baseline: 1.0592x; 1.0592x over previous
#include <cuda_runtime.h>
#include <math.h>
#include <stdint.h>

// ---------------- problem constants ----------------
#define Bx 16
#define Sx 384
#define Hx 768
#define DKx 64
#define ESSx 6
#define WHOLEx 8
#define HEADERx 9
#define IGx 672
#define IPx 960
#define H2x 1536
#define Px 73920              // S*(S+1)/2
#define Mx (Bx*Sx)            // 6144

// ---------------- scratch (device globals; no allocations) ----------------
__device__ float g_cos[Sx*32];
__device__ float g_sin[Sx*32];
__device__ float g_lin[Mx*576];
__device__ float g_hid[Mx*IPx];
__device__ float g_tsq[Bx*Sx*DKx];
__device__ float g_tsk[Bx*Sx*DKx];
__device__ float g_qg [Bx*HEADERx*Sx*DKx];
__device__ float g_kg [Bx*HEADERx*Sx*DKx];
__device__ float g_scg[(size_t)Bx*HEADERx*Sx*Sx];
__device__ float g_adj[(size_t)Bx*HEADERx*Sx*Sx];
__device__ float g_hr [(size_t)HEADERx*Bx*Sx*Hx];
__device__ float g_feat[Mx*Hx];
__device__ float g_agg [Mx*Hx];
__device__ float g_inp [Mx*H2x];
__device__ float g_tq[Bx*Sx*DKx];
__device__ float g_tk[Bx*Sx*DKx];
__device__ float g_qp[Bx*ESSx*Sx*DKx];
__device__ float g_kp[Bx*ESSx*Sx*DKx];
__device__ float g_stg[(size_t)Bx*Sx*Sx];
__device__ float g_stp[(size_t)Bx*Sx*Sx];
__device__ float g_sp [(size_t)Bx*ESSx*Sx*Sx];

// ---------------- rope tables ----------------
__global__ void k_init_rope() {
    int idx = blockIdx.x * blockDim.x + threadIdx.x;
    if (idx >= Sx * 32) return;
    int p = idx / 32, i = idx & 31;
    double theta = (double)p * pow(10000.0, -(double)i / 32.0);
    g_cos[idx] = (float)cos(theta);
    g_sin[idx] = (float)sin(theta);
}

// ---------------- tf32 helpers ----------------
__device__ __forceinline__ uint32_t f2tf(float x) {
    uint32_t r;
    asm("cvt.rna.tf32.f32 %0, %1;" : "=r"(r) : "f"(x));
    return r;
}

__device__ __forceinline__ void mma_tf32(float* d, const uint32_t* a, const uint32_t* b) {
    asm volatile(
        "mma.sync.aligned.m16n8k8.row.col.f32.tf32.tf32.f32 "
        "{%0,%1,%2,%3},{%4,%5,%6,%7},{%8,%9},{%0,%1,%2,%3};"
        : "+f"(d[0]), "+f"(d[1]), "+f"(d[2]), "+f"(d[3])
        : "r"(a[0]), "r"(a[1]), "r"(a[2]), "r"(a[3]), "r"(b[0]), "r"(b[1]));
}

#define SWX(k) (((((k) >> 2) & 3)) << 3)

// ---------------- 3xTF32 tensor-core GEMM:  C[z] = act( A[z] @ W[z]^T * scale + bias ) ----------------
// BM=BN=128, BK=16, 512 threads (16 warps 4x4), warp tile 32x32.
// M % 128 == 0, K % 16 == 0, N arbitrary (even), guarded.
__global__ void __launch_bounds__(512) k_mma(
    const float* __restrict__ A, long astr,
    const float* __restrict__ W, long wstr,
    const float* __restrict__ bias,
    float* __restrict__ C, long cstr,
    int M, int N, int K, int relu, float scale)
{
    __shared__ uint32_t Ah[16][136], Al[16][136], Bh[16][136], Bl[16][136];

    const float* Az = A + (long)blockIdx.z * astr;
    const float* Wz = W + (long)blockIdx.z * wstr;
    float* Cz = C + (long)blockIdx.z * cstr;

    int tid = threadIdx.x, lane = tid & 31;
    int g = lane >> 2, tg = lane & 3;
    int wid = tid >> 5, wm = wid >> 2, wn = wid & 3;
    int row0 = blockIdx.y * 128, col0 = blockIdx.x * 128;
    int lr = tid >> 2, lk = (tid & 3) * 4;

    float acc[2][4][4] = {};

    const float* ap = Az + (long)(row0 + lr) * K + lk;
    bool wok = (col0 + lr) < N;
    const float* wp = Wz + (long)(wok ? (col0 + lr) : 0) * K + lk;

    for (int k0 = 0; k0 < K; k0 += 16) {
        float4 av = *(const float4*)ap; ap += 16;
        float4 wv = wok ? *(const float4*)wp : make_float4(0.f,0.f,0.f,0.f); wp += 16;
        float va[4] = {av.x, av.y, av.z, av.w};
        float vw[4] = {wv.x, wv.y, wv.z, wv.w};
#pragma unroll
        for (int j = 0; j < 4; ++j) {
            int kk = lk + j;
            int c = lr ^ SWX(kk);
            uint32_t h = f2tf(va[j]);
            Ah[kk][c] = h;
            Al[kk][c] = f2tf(va[j] - __uint_as_float(h));
            uint32_t hw = f2tf(vw[j]);
            Bh[kk][c] = hw;
            Bl[kk][c] = f2tf(vw[j] - __uint_as_float(hw));
        }
        __syncthreads();

#pragma unroll
        for (int ks = 0; ks < 16; ks += 8) {
            int k1 = ks + tg, k2 = ks + tg + 4;
            int x1 = SWX(k1), x2 = SWX(k2);
            uint32_t ah[2][4], al[2][4], bh[4][2], bl[4][2];
#pragma unroll
            for (int mt = 0; mt < 2; ++mt) {
                int r = wm * 32 + mt * 16 + g;
                ah[mt][0] = Ah[k1][r ^ x1];       ah[mt][1] = Ah[k1][(r + 8) ^ x1];
                ah[mt][2] = Ah[k2][r ^ x2];       ah[mt][3] = Ah[k2][(r + 8) ^ x2];
                al[mt][0] = Al[k1][r ^ x1];       al[mt][1] = Al[k1][(r + 8) ^ x1];
                al[mt][2] = Al[k2][r ^ x2];       al[mt][3] = Al[k2][(r + 8) ^ x2];
            }
#pragma unroll
            for (int nt = 0; nt < 4; ++nt) {
                int c = wn * 32 + nt * 8 + g;
                bh[nt][0] = Bh[k1][c ^ x1];       bh[nt][1] = Bh[k2][c ^ x2];
                bl[nt][0] = Bl[k1][c ^ x1];       bl[nt][1] = Bl[k2][c ^ x2];
            }
#pragma unroll
            for (int mt = 0; mt < 2; ++mt)
#pragma unroll
                for (int nt = 0; nt < 4; ++nt) {
                    mma_tf32(acc[mt][nt], al[mt], bh[nt]);
                    mma_tf32(acc[mt][nt], ah[mt], bl[nt]);
                    mma_tf32(acc[mt][nt], ah[mt], bh[nt]);
                }
        }
        __syncthreads();
    }

#pragma unroll
    for (int mt = 0; mt < 2; ++mt) {
        int r = row0 + wm * 32 + mt * 16 + g;
#pragma unroll
        for (int nt = 0; nt < 4; ++nt) {
            int c = col0 + wn * 32 + nt * 8 + 2 * tg;
            if (c < N) {
                float b0v = bias ? bias[c] : 0.f;
                float b1v = bias ? bias[c + 1] : 0.f;
                float2 v0 = make_float2(acc[mt][nt][0] * scale + b0v,
                                        acc[mt][nt][1] * scale + b1v);
                float2 v1 = make_float2(acc[mt][nt][2] * scale + b0v,
                                        acc[mt][nt][3] * scale + b1v);
                if (relu) {
                    v0.x = fmaxf(v0.x, 0.f); v0.y = fmaxf(v0.y, 0.f);
                    v1.x = fmaxf(v1.x, 0.f); v1.y = fmaxf(v1.y, 0.f);
                }
                *(float2*)&Cz[(long)r * N + c] = v0;
                *(float2*)&Cz[(long)(r + 8) * N + c] = v1;
            }
        }
    }
}

// ---------------- 3xTF32 fused RGAT aggregation: out[b] = sum_r relu( adj[b,r] @ hr[r,b] ) ----------------
// BM=128 (s), BN=64 (o), BK=16, 256 threads (8 warps 4x2), warp tile 32x32.
__global__ void __launch_bounds__(256) k_mma_agg(
    const float* __restrict__ adj, const float* __restrict__ hr,
    float* __restrict__ out)
{
    __shared__ uint32_t Ah[16][136], Al[16][136], Bh[16][72], Bl[16][72];

    int b = blockIdx.z;
    int row0 = blockIdx.y * 128, col0 = blockIdx.x * 64;

    int tid = threadIdx.x, lane = tid & 31;
    int g = lane >> 2, tg = lane & 3;
    int wid = tid >> 5, wm = wid >> 1, wn = wid & 1;
    int lr = tid >> 1, lk = (tid & 1) * 8;       // adj tile loader
    int kr = tid >> 4, kc = (tid & 15) * 4;      // hr tile loader

    float sum[2][4][4] = {};

    for (int r = 0; r < HEADERx; ++r) {
        const float* adjbr = adj + ((long)(b * HEADERx + r)) * Sx * Sx;
        const float* hrrb  = hr  + ((long)(r * Bx + b)) * Sx * Hx;
        float acc[2][4][4] = {};

        for (int k0 = 0; k0 < Sx; k0 += 16) {
            const float* ap = adjbr + (long)(row0 + lr) * Sx + k0 + lk;
            float4 a0 = *(const float4*)ap;
            float4 a1 = *(const float4*)(ap + 4);
            float va[8] = {a0.x,a0.y,a0.z,a0.w,a1.x,a1.y,a1.z,a1.w};
#pragma unroll
            for (int j = 0; j < 8; ++j) {
                int kk = lk + j;
                int c = lr ^ SWX(kk);
                uint32_t h = f2tf(va[j]);
                Ah[kk][c] = h;
                Al[kk][c] = f2tf(va[j] - __uint_as_float(h));
            }
            const float* bp = hrrb + (long)(k0 + kr) * Hx + col0 + kc;
            float4 bv = *(const float4*)bp;
            {
                int c = kc ^ SWX(kr);
                float vb[4] = {bv.x, bv.y, bv.z, bv.w};
#pragma unroll
                for (int j = 0; j < 4; ++j) {
                    uint32_t h = f2tf(vb[j]);
                    Bh[kr][c + j] = h;
                    Bl[kr][c + j] = f2tf(vb[j] - __uint_as_float(h));
                }
            }
            __syncthreads();

#pragma unroll
            for (int ks = 0; ks < 16; ks += 8) {
                int k1 = ks + tg, k2 = ks + tg + 4;
                int x1 = SWX(k1), x2 = SWX(k2);
                uint32_t ah[2][4], al[2][4], bh[4][2], bl[4][2];
#pragma unroll
                for (int mt = 0; mt < 2; ++mt) {
                    int rr = wm * 32 + mt * 16 + g;
                    ah[mt][0] = Ah[k1][rr ^ x1];       ah[mt][1] = Ah[k1][(rr + 8) ^ x1];
                    ah[mt][2] = Ah[k2][rr ^ x2];       ah[mt][3] = Ah[k2][(rr + 8) ^ x2];
                    al[mt][0] = Al[k1][rr ^ x1];       al[mt][1] = Al[k1][(rr + 8) ^ x1];
                    al[mt][2] = Al[k2][rr ^ x2];       al[mt][3] = Al[k2][(rr + 8) ^ x2];
                }
#pragma unroll
                for (int nt = 0; nt < 4; ++nt) {
                    int c = wn * 32 + nt * 8 + g;
                    bh[nt][0] = Bh[k1][c ^ x1];        bh[nt][1] = Bh[k2][c ^ x2];
                    bl[nt][0] = Bl[k1][c ^ x1];        bl[nt][1] = Bl[k2][c ^ x2];
                }
#pragma unroll
                for (int mt = 0; mt < 2; ++mt)
#pragma unroll
                    for (int nt = 0; nt < 4; ++nt) {
                        mma_tf32(acc[mt][nt], al[mt], bh[nt]);
                        mma_tf32(acc[mt][nt], ah[mt], bl[nt]);
                        mma_tf32(acc[mt][nt], ah[mt], bh[nt]);
                    }
            }
            __syncthreads();
        }
#pragma unroll
        for (int mt = 0; mt < 2; ++mt)
#pragma unroll
            for (int nt = 0; nt < 4; ++nt)
#pragma unroll
                for (int i = 0; i < 4; ++i)
                    sum[mt][nt][i] += fmaxf(acc[mt][nt][i], 0.f);
    }

#pragma unroll
    for (int mt = 0; mt < 2; ++mt) {
        int s = row0 + wm * 32 + mt * 16 + g;
#pragma unroll
        for (int nt = 0; nt < 4; ++nt) {
            int o = col0 + wn * 32 + nt * 8 + 2 * tg;
            float2 v0 = make_float2(sum[mt][nt][0], sum[mt][nt][1]);
            float2 v1 = make_float2(sum[mt][nt][2], sum[mt][nt][3]);
            *(float2*)&out[((long)b * Sx + s) * Hx + o] = v0;
            *(float2*)&out[((long)b * Sx + s + 8) * Hx + o] = v1;
        }
    }
}

// ---------------- mask + RoPE + head split ----------------
__global__ void k_rope(const float* __restrict__ lin, const float* __restrict__ mask,
                       float* __restrict__ out, int nH)
{
    int bs = blockIdx.x;
    int b = bs / Sx, s = bs % Sx;
    float m = mask[bs];
    int t = threadIdx.x;
    int h = t >> 5, i = t & 31;
    float c  = g_cos[s*32 + i];
    float sn = g_sin[s*32 + i];
    const float* lp = lin + (long)bs * nH * 64 + h * 64 + 2*i;
    float x0 = lp[0] * m, x1 = lp[1] * m;
    float* op = out + (((long)(b*nH + h)) * Sx + s) * 64 + 2*i;
    op[0] = x0 * c - x1 * sn;
    op[1] = x1 * c + x0 * sn;
}

// ---------------- symmetric softmax -> adj ----------------
__global__ void k_adj(const float* __restrict__ score, float* __restrict__ adj)
{
    int blk = blockIdx.x;
    int i = blk % Sx;
    long bh = blk / Sx;
    const float* sc = score + bh * (long)(Sx*Sx);
    float* out = adj + bh * (long)(Sx*Sx) + (long)i * Sx;
    int t = threadIdx.x;
    float v[3];
#pragma unroll
    for (int u = 0; u < 3; ++u) {
        int j = t + u * 128;
        v[u] = (j >= i) ? sc[(long)i*Sx + j] : sc[(long)j*Sx + i];
    }
    __shared__ float red[128];
    float m = fmaxf(v[0], fmaxf(v[1], v[2]));
    red[t] = m; __syncthreads();
#pragma unroll
    for (int st = 64; st > 0; st >>= 1) {
        if (t < st) red[t] = fmaxf(red[t], red[t + st]);
        __syncthreads();
    }
    m = red[0]; __syncthreads();
    float e0 = expf(v[0]-m), e1 = expf(v[1]-m), e2 = expf(v[2]-m);
    red[t] = e0 + e1 + e2; __syncthreads();
#pragma unroll
    for (int st = 64; st > 0; st >>= 1) {
        if (t < st) red[t] += red[t + st];
        __syncthreads();
    }
    float is = 1.f / red[0];
    out[t      ] = (v[0] != 0.f) ? e0 * is : 0.f;
    out[t + 128] = (v[1] != 0.f) ? e1 * is : 0.f;
    out[t + 256] = (v[2] != 0.f) ? e2 * is : 0.f;
}

// ---------------- feat = layernorm( relu(agg)/9 ) ----------------
__global__ void k_ln(const float* __restrict__ a, float* __restrict__ o)
{
    long bs = blockIdx.x;
    const float* x = a + bs * Hx;
    float* y = o + bs * Hx;
    int t = threadIdx.x;
    float v[3];
    float s = 0.f;
#pragma unroll
    for (int u = 0; u < 3; ++u) {
        v[u] = fmaxf(x[t + u*256], 0.f) * (1.f/9.f);
        s += v[u];
    }
    __shared__ float red[256];
    red[t] = s; __syncthreads();
#pragma unroll
    for (int st = 128; st > 0; st >>= 1) {
        if (t < st) red[t] += red[t + st];
        __syncthreads();
    }
    float mean = red[0] * (1.f/768.f); __syncthreads();
    float s2 = 0.f;
#pragma unroll
    for (int u = 0; u < 3; ++u) { float d = v[u] - mean; s2 += d*d; }
    red[t] = s2; __syncthreads();
#pragma unroll
    for (int st = 128; st > 0; st >>= 1) {
        if (t < st) red[t] += red[t + st];
        __syncthreads();
    }
    float var = red[0] * (1.f/768.f);
    float rr = rsqrtf(var + 1e-5f);
#pragma unroll
    for (int u = 0; u < 3; ++u) y[t + u*256] = (v[u] - mean) * rr;
}

// ---------------- inp = concat(x, feat) ----------------
__global__ void k_concat(const float* __restrict__ x, const float* __restrict__ feat,
                         float* __restrict__ inp)
{
    long idx = (long)blockIdx.x * blockDim.x + threadIdx.x;
    if (idx >= (long)Mx * H2x) return;
    long row = idx / H2x;
    int c = (int)(idx % H2x);
    inp[idx] = (c < Hx) ? x[row * Hx + c] : feat[row * Hx + (c - Hx)];
}

// ---------------- gather upper-triangle pairs -> out[B,P,16] ----------------
__global__ void k_pairs(const float* __restrict__ sp, const float* __restrict__ stp,
                        const float* __restrict__ sg, const float* __restrict__ stg,
                        float* __restrict__ out)
{
    int i = blockIdx.x, b = blockIdx.y, j = threadIdx.x;
    if (j < i) return;
    long p  = (long)i * (2*Sx - i + 1) / 2 + (j - i);
    long ss = (long)Sx * Sx;
    long ij = (long)i * Sx + j;
    const float* spb = sp + (long)b * ESSx * ss + ij;
    const float* sgb = sg + (long)b * HEADERx * ss + ij;
    float4 o0, o1, o2, o3;
    o0.x = spb[0];     o0.y = spb[ss];   o0.z = spb[2*ss]; o0.w = spb[3*ss];
    o1.x = spb[4*ss];  o1.y = spb[5*ss];
    o1.z = fmaxf(stp[(long)b*ss + ij], 0.f);
    o1.w = sgb[0];
    o2.x = sgb[ss];    o2.y = sgb[2*ss]; o2.z = sgb[3*ss]; o2.w = sgb[4*ss];
    o3.x = sgb[5*ss];  o3.y = sgb[6*ss]; o3.z = sgb[7*ss];
    o3.w = fmaxf(stg[(long)b*ss + ij], 0.f);
    float4* op = (float4*)(out + ((long)b * Px + p) * 16);
    op[0] = o0; op[1] = o1; op[2] = o2; op[3] = o3;
}

// ---------------- host ----------------
static void launch_gemm(const float* A, long astr, const float* W, long wstr,
                        const float* bias, float* C, long cstr,
                        int M, int N, int K, int relu, float scale, int Z)
{
    dim3 grid((N + 127) / 128, M / 128, Z);
    k_mma<<<grid, 512>>>(A, astr, W, wstr, bias, C, cstr, M, N, K, relu, scale);
}

extern "C" void kernel_launch(void* const* d_in, const int* in_sizes, int n_in,
                              void* d_out, int out_size)
{
    const float* x          = (const float*)d_in[0];
    const float* amask      = (const float*)d_in[1];
    const float* wq4gt_w    = (const float*)d_in[2];
    const float* wq4gt_b    = (const float*)d_in[3];
    const float* wk4gt_w    = (const float*)d_in[4];
    const float* wk4gt_b    = (const float*)d_in[5];
    const float* wq4g_rep_w = (const float*)d_in[6];
    const float* wq4g_rep_b = (const float*)d_in[7];
    const float* wq4g_sc_w  = (const float*)d_in[8];
    const float* wq4g_sc_b  = (const float*)d_in[9];
    const float* wk4g_rep_w = (const float*)d_in[10];
    const float* wk4g_rep_b = (const float*)d_in[11];
    const float* wk4g_sc_w  = (const float*)d_in[12];
    const float* wk4g_sc_b  = (const float*)d_in[13];
    const float* rgat_w     = (const float*)d_in[14];
    const float* wq4t_w     = (const float*)d_in[15];
    const float* wq4t_b     = (const float*)d_in[16];
    const float* wk4t_w     = (const float*)d_in[17];
    const float* wk4t_b     = (const float*)d_in[18];
    const float* wq_rep_w   = (const float*)d_in[19];
    const float* wq_rep_b   = (const float*)d_in[20];
    const float* wq_sc_w    = (const float*)d_in[21];
    const float* wq_sc_b    = (const float*)d_in[22];
    const float* wk_rep_w   = (const float*)d_in[23];
    const float* wk_rep_b   = (const float*)d_in[24];
    const float* wk_sc_w    = (const float*)d_in[25];
    const float* wk_sc_b    = (const float*)d_in[26];
    float* out = (float*)d_out;

    float *lin,*hid,*tsq,*tsk,*qg,*kg,*scg,*adj,*hr,*feat,*agg,*inp,*tq,*tk,*qp,*kp,*stg,*stp,*sp;
    cudaGetSymbolAddress((void**)&lin,  g_lin);
    cudaGetSymbolAddress((void**)&hid,  g_hid);
    cudaGetSymbolAddress((void**)&tsq,  g_tsq);
    cudaGetSymbolAddress((void**)&tsk,  g_tsk);
    cudaGetSymbolAddress((void**)&qg,   g_qg);
    cudaGetSymbolAddress((void**)&kg,   g_kg);
    cudaGetSymbolAddress((void**)&scg,  g_scg);
    cudaGetSymbolAddress((void**)&adj,  g_adj);
    cudaGetSymbolAddress((void**)&hr,   g_hr);
    cudaGetSymbolAddress((void**)&feat, g_feat);
    cudaGetSymbolAddress((void**)&agg,  g_agg);
    cudaGetSymbolAddress((void**)&inp,  g_inp);
    cudaGetSymbolAddress((void**)&tq,   g_tq);
    cudaGetSymbolAddress((void**)&tk,   g_tk);
    cudaGetSymbolAddress((void**)&qp,   g_qp);
    cudaGetSymbolAddress((void**)&kp,   g_kp);
    cudaGetSymbolAddress((void**)&stg,  g_stg);
    cudaGetSymbolAddress((void**)&stp,  g_stp);
    cudaGetSymbolAddress((void**)&sp,   g_sp);

    const float inv = 0.125f;
    const long sd  = (long)Sx * DKx;
    const long ss  = (long)Sx * Sx;

    k_init_rope<<<48, 256>>>();

    // ---- graph threshold heads ----
    launch_gemm(x, 0, wq4gt_w, 0, wq4gt_b, lin, 0, Mx, 64, Hx, 0, 1.f, 1);
    k_rope<<<Mx, 32>>>(lin, amask, tsq, 1);
    launch_gemm(x, 0, wk4gt_w, 0, wk4gt_b, lin, 0, Mx, 64, Hx, 0, 1.f, 1);
    k_rope<<<Mx, 32>>>(lin, amask, tsk, 1);
    launch_gemm(tsq, sd, tsk, sd, nullptr, stg, ss, Sx, Sx, DKx, 0, inv, Bx);

    // ---- graph q/k (9 heads) ----
    launch_gemm(x, 0, wq4g_rep_w, 0, wq4g_rep_b, hid, 0, Mx, IGx, Hx, 1, 1.f, 1);
    launch_gemm(hid, 0, wq4g_sc_w, 0, wq4g_sc_b, lin, 0, Mx, 576, IGx, 0, 1.f, 1);
    k_rope<<<Mx, 288>>>(lin, amask, qg, 9);
    launch_gemm(x, 0, wk4g_rep_w, 0, wk4g_rep_b, hid, 0, Mx, IGx, Hx, 1, 1.f, 1);
    launch_gemm(hid, 0, wk4g_sc_w, 0, wk4g_sc_b, lin, 0, Mx, 576, IGx, 0, 1.f, 1);
    k_rope<<<Mx, 288>>>(lin, amask, kg, 9);
    launch_gemm(qg, sd, kg, sd, nullptr, scg, ss, Sx, Sx, DKx, 0, inv, Bx*HEADERx);
    k_adj<<<Bx*HEADERx*Sx, 128>>>(scg, adj);

    // ---- RGAT (2 layers) ----
    const float* f = x;
    for (int l = 0; l < 2; ++l) {
        launch_gemm(f, 0, rgat_w + (long)l*HEADERx*Hx*Hx, (long)Hx*Hx, nullptr,
                    hr, (long)Bx*Sx*Hx, Mx, Hx, Hx, 0, 1.f, HEADERx);
        k_mma_agg<<<dim3(Hx/64, Sx/128, Bx), 256>>>(adj, hr, agg);
        k_ln<<<Mx, 256>>>(agg, feat);
        f = feat;
    }

    // ---- concat ----
    k_concat<<<((long)Mx*H2x + 255)/256, 256>>>(x, feat, inp);

    // ---- prediction threshold heads ----
    launch_gemm(inp, 0, wq4t_w, 0, wq4t_b, lin, 0, Mx, 64, H2x, 0, 1.f, 1);
    k_rope<<<Mx, 32>>>(lin, amask, tq, 1);
    launch_gemm(inp, 0, wk4t_w, 0, wk4t_b, lin, 0, Mx, 64, H2x, 0, 1.f, 1);
    k_rope<<<Mx, 32>>>(lin, amask, tk, 1);
    launch_gemm(tq, sd, tk, sd, nullptr, stp, ss, Sx, Sx, DKx, 0, inv, Bx);

    // ---- prediction q/k (6 heads) ----
    launch_gemm(inp, 0, wq_rep_w, 0, wq_rep_b, hid, 0, Mx, IPx, H2x, 1, 1.f, 1);
    launch_gemm(hid, 0, wq_sc_w, 0, wq_sc_b, lin, 0, Mx, 384, IPx, 0, 1.f, 1);
    k_rope<<<Mx, 192>>>(lin, amask, qp, 6);
    launch_gemm(inp, 0, wk_rep_w, 0, wk_rep_b, hid, 0, Mx, IPx, H2x, 1, 1.f, 1);
    launch_gemm(hid, 0, wk_sc_w, 0, wk_sc_b, lin, 0, Mx, 384, IPx, 0, 1.f, 1);
    k_rope<<<Mx, 192>>>(lin, amask, kp, 6);
    launch_gemm(qp, sd, kp, sd, nullptr, sp, ss, Sx, Sx, DKx, 0, inv, Bx*ESSx);

    // ---- final gather ----
    k_pairs<<<dim3(Sx, Bx), Sx>>>(sp, stp, scg, stg, out);
}